// round 1
// baseline (speedup 1.0000x reference)
#include <cuda_runtime.h>
#include <cuda_bf16.h>
#include <math.h>

// Problem constants
#define Bb   4
#define Tt   4096
#define Dd   1024
#define Hh   16
#define DH   64
#define Mm   (Bb*Tt)          // 16384 rows
#define NELEM (Mm*Dd)         // 16,777,216

// ---------------- scratch (device globals; no allocation allowed) -------------
__device__ float g_xn [NELEM];
__device__ float g_q  [NELEM];
__device__ float g_k  [NELEM];
__device__ float g_v  [NELEM];
__device__ float g_y  [NELEM];
__device__ float g_h  [NELEM];
__device__ float g_ctx[Bb*Hh*DH*DH];      // 262144
__device__ float g_ss [Bb*2*Dd];          // scale/shift, 8192
__device__ float g_pm [8*Bb*Dd];          // k-softmax partial max
__device__ float g_ps [8*Bb*Dd];          // k-softmax partial sum
__device__ float g_m  [Bb*Dd];
__device__ float g_s  [Bb*Dd];

// ---------------- helpers ----------------
__device__ __forceinline__ float warpSum(float v) {
    #pragma unroll
    for (int o = 16; o > 0; o >>= 1) v += __shfl_xor_sync(0xffffffffu, v, o);
    return v;
}
__device__ __forceinline__ float warpMax(float v) {
    #pragma unroll
    for (int o = 16; o > 0; o >>= 1) v = fmaxf(v, __shfl_xor_sync(0xffffffffu, v, o));
    return v;
}
__device__ __forceinline__ float siluf(float v) {
    return v / (1.0f + expf(-v));
}

// ---------------- LayerNorm 1: x -> xn ----------------
__global__ __launch_bounds__(256)
void ln1_kernel(const float* __restrict__ x, const float* __restrict__ g,
                const float* __restrict__ b, float* __restrict__ out)
{
    const int row = blockIdx.x;
    const float* xr = x + (size_t)row * Dd;
    float4 xv = *(const float4*)(xr + threadIdx.x * 4);
    float s  = xv.x + xv.y + xv.z + xv.w;
    float s2 = xv.x*xv.x + xv.y*xv.y + xv.z*xv.z + xv.w*xv.w;

    __shared__ float sh1[8], sh2[8], bc[2];
    s = warpSum(s); s2 = warpSum(s2);
    int w = threadIdx.x >> 5;
    if ((threadIdx.x & 31) == 0) { sh1[w] = s; sh2[w] = s2; }
    __syncthreads();
    if (threadIdx.x == 0) {
        float a = 0.f, c = 0.f;
        #pragma unroll
        for (int i = 0; i < 8; i++) { a += sh1[i]; c += sh2[i]; }
        bc[0] = a; bc[1] = c;
    }
    __syncthreads();
    float mu  = bc[0] * (1.0f / Dd);
    float var = bc[1] * (1.0f / Dd) - mu * mu;
    float inv = rsqrtf(var + 1e-5f);

    int d = threadIdx.x * 4;
    float4 gv = *(const float4*)(g + d);
    float4 bv = *(const float4*)(b + d);
    float4 o;
    o.x = (xv.x - mu) * inv * gv.x + bv.x;
    o.y = (xv.y - mu) * inv * gv.y + bv.y;
    o.z = (xv.z - mu) * inv * gv.z + bv.z;
    o.w = (xv.w - mu) * inv * gv.w + bv.w;
    *(float4*)(out + (size_t)row * Dd + d) = o;
}

// ---------------- SGEMM 128x128x8, 8x8/thread ----------------
// EPI=0: C = A*W + bias
// EPI=1: C = resid + gate[b] * (A*W + bias)   (b = row / Trows)
template<int EPI>
__global__ __launch_bounds__(256)
void sgemm_k(const float* __restrict__ A, const float* __restrict__ W,
             const float* __restrict__ bias, float* __restrict__ C,
             const float* __restrict__ resid, const float* __restrict__ gate,
             int M, int N, int K, int Trows)
{
    const int BM = 128, BN = 128, BK = 8, TM = 8, TN = 8;
    __shared__ float As[BK][BM];
    __shared__ float Bs[BK][BN];

    const int tid  = threadIdx.x;
    const int cRow = blockIdx.y * BM;
    const int cCol = blockIdx.x * BN;
    const int tRow = (tid / 16) * TM;
    const int tCol = (tid % 16) * TN;

    const int aRow = tid >> 1;            // 0..127
    const int aCol = (tid & 1) * 4;       // 0 or 4
    const int bRow = tid >> 5;            // 0..7
    const int bCol = (tid & 31) * 4;      // 0..124

    float acc[TM][TN] = {};

    const float* Aptr = A + (size_t)(cRow + aRow) * K + aCol;
    const float* Wptr = W + cCol + bCol;

    for (int k0 = 0; k0 < K; k0 += BK) {
        float4 a = *(const float4*)(Aptr + k0);
        As[aCol + 0][aRow] = a.x;
        As[aCol + 1][aRow] = a.y;
        As[aCol + 2][aRow] = a.z;
        As[aCol + 3][aRow] = a.w;
        float4 bv = *(const float4*)(Wptr + (size_t)(k0 + bRow) * N);
        *(float4*)&Bs[bRow][bCol] = bv;
        __syncthreads();

        #pragma unroll
        for (int k = 0; k < BK; k++) {
            float rm[TM], rn[TN];
            #pragma unroll
            for (int i = 0; i < TM; i++) rm[i] = As[k][tRow + i];
            #pragma unroll
            for (int j = 0; j < TN; j++) rn[j] = Bs[k][tCol + j];
            #pragma unroll
            for (int i = 0; i < TM; i++)
                #pragma unroll
                for (int j = 0; j < TN; j++)
                    acc[i][j] += rm[i] * rn[j];
        }
        __syncthreads();
    }

    #pragma unroll
    for (int i = 0; i < TM; i++) {
        int row = cRow + tRow + i;
        #pragma unroll
        for (int j = 0; j < TN; j += 4) {
            int col = cCol + tCol + j;
            float4 v;
            v.x = acc[i][j+0] + bias[col+0];
            v.y = acc[i][j+1] + bias[col+1];
            v.z = acc[i][j+2] + bias[col+2];
            v.w = acc[i][j+3] + bias[col+3];
            if (EPI == 1) {
                int bb = row / Trows;
                const float* gp = gate + (size_t)bb * N + col;
                float4 r = *(const float4*)(resid + (size_t)row * N + col);
                v.x = r.x + gp[0] * v.x;
                v.y = r.y + gp[1] * v.y;
                v.z = r.z + gp[2] * v.z;
                v.w = r.w + gp[3] * v.w;
            }
            *(float4*)(C + (size_t)row * N + col) = v;
        }
    }
}

// ---------------- q feature-softmax: rows of 64, one warp per row ----------------
__global__ __launch_bounds__(256)
void qsm_kernel(float* __restrict__ q)
{
    int gwarp = (blockIdx.x * blockDim.x + threadIdx.x) >> 5;  // 0..262143
    int lane  = threadIdx.x & 31;
    float2 v = *(float2*)(q + (size_t)gwarp * 64 + lane * 2);
    float m = warpMax(fmaxf(v.x, v.y));
    float e0 = expf(v.x - m), e1 = expf(v.y - m);
    float s = warpSum(e0 + e1);
    float inv = 1.0f / s;
    float2 o; o.x = e0 * inv; o.y = e1 * inv;
    *(float2*)(q + (size_t)gwarp * 64 + lane * 2) = o;
}

// ---------------- k temporal softmax (axis=T), split into 8 T-chunks ----------------
__global__ __launch_bounds__(256)
void ksm_part(const float* __restrict__ k, float* __restrict__ pm, float* __restrict__ ps)
{
    int col = blockIdx.x * 256 + threadIdx.x;   // 0..4095  (b*1024 + d)
    int b = col >> 10, d = col & 1023;
    int t0 = blockIdx.y * (Tt / 8);
    const float* p = k + ((size_t)(b * Tt + t0)) * Dd + d;
    float m = -INFINITY, s = 0.0f;
    #pragma unroll 4
    for (int t = 0; t < Tt / 8; t++) {
        float v = p[(size_t)t * Dd];
        float mn = fmaxf(m, v);
        s = s * expf(m - mn) + expf(v - mn);
        m = mn;
    }
    pm[blockIdx.y * (Bb * Dd) + col] = m;
    ps[blockIdx.y * (Bb * Dd) + col] = s;
}

__global__ __launch_bounds__(256)
void ksm_comb(const float* __restrict__ pm, const float* __restrict__ ps,
              float* __restrict__ gm, float* __restrict__ gs)
{
    int col = blockIdx.x * 256 + threadIdx.x;
    float M = -INFINITY;
    #pragma unroll
    for (int c = 0; c < 8; c++) M = fmaxf(M, pm[c * (Bb * Dd) + col]);
    float S = 0.0f;
    #pragma unroll
    for (int c = 0; c < 8; c++)
        S += ps[c * (Bb * Dd) + col] * expf(pm[c * (Bb * Dd) + col] - M);
    gm[col] = M;
    gs[col] = S;
}

__global__ __launch_bounds__(256)
void ksm_norm(float* __restrict__ k, const float* __restrict__ gm, const float* __restrict__ gs)
{
    size_t i4 = (size_t)blockIdx.x * 256 + threadIdx.x;  // float4 index
    size_t e  = i4 * 4;
    int b = (int)(e >> 22);              // / (T*D)
    int d = (int)(e & 1023);
    int col = b * 1024 + d;
    float4 v = *(float4*)(k + e);
    float4 m = *(const float4*)(gm + col);
    float4 s = *(const float4*)(gs + col);
    float4 o;
    o.x = expf(v.x - m.x) / s.x;
    o.y = expf(v.y - m.y) / s.y;
    o.z = expf(v.z - m.z) / s.z;
    o.w = expf(v.w - m.w) / s.w;
    *(float4*)(k + e) = o;
}

// ---------------- zero ctx ----------------
__global__ void zero_kernel(float* __restrict__ p, int n)
{
    int i = blockIdx.x * blockDim.x + threadIdx.x;
    if (i < n) p[i] = 0.0f;
}

// ---------------- ctx[b,h,d,l] = sum_t k[b,t,h,d] * v[b,t,h,l] ----------------
// grid: (B*H, 8 T-chunks); block 256 (16x16, 4x4 per thread); atomicAdd combine.
__global__ __launch_bounds__(256)
void ctx_kernel(const float* __restrict__ k, const float* __restrict__ v,
                float* __restrict__ ctx)
{
    int bh = blockIdx.x;
    int b = bh >> 4, h = bh & 15;
    __shared__ float ks[64][64];
    __shared__ float vs[64][64];
    int tr = threadIdx.x >> 4, tc = threadIdx.x & 15;
    float acc[4][4] = {};

    int tbase = blockIdx.y * (Tt / 8);
    for (int tt0 = 0; tt0 < Tt / 8; tt0 += 64) {
        for (int i = threadIdx.x; i < 64 * 16; i += 256) {
            int t  = i >> 4;
            int c4 = (i & 15) * 4;
            size_t off = ((size_t)((b * Tt + tbase + tt0 + t)) * Hh + h) * DH + c4;
            *(float4*)&ks[t][c4] = *(const float4*)(k + off);
            *(float4*)&vs[t][c4] = *(const float4*)(v + off);
        }
        __syncthreads();
        #pragma unroll 8
        for (int t = 0; t < 64; t++) {
            float rk[4], rv[4];
            #pragma unroll
            for (int i = 0; i < 4; i++) rk[i] = ks[t][tr * 4 + i];
            #pragma unroll
            for (int j = 0; j < 4; j++) rv[j] = vs[t][tc * 4 + j];
            #pragma unroll
            for (int i = 0; i < 4; i++)
                #pragma unroll
                for (int j = 0; j < 4; j++)
                    acc[i][j] += rk[i] * rv[j];
        }
        __syncthreads();
    }
    float* c = ctx + (size_t)bh * (DH * DH);
    #pragma unroll
    for (int i = 0; i < 4; i++)
        #pragma unroll
        for (int j = 0; j < 4; j++)
            atomicAdd(&c[(tr * 4 + i) * DH + tc * 4 + j], acc[i][j]);
}

// ---------------- y[b,t,h,:] = q[b,t,h,:] @ ctx[b,h] ----------------
// grid: (B*H, T/256); block 256; one t per thread; ctx tile in smem.
__global__ __launch_bounds__(256)
void y_kernel(const float* __restrict__ q, const float* __restrict__ ctx,
              float* __restrict__ y)
{
    int bh = blockIdx.x;
    int b = bh >> 4, h = bh & 15;
    __shared__ float cs[DH * DH];
    for (int i = threadIdx.x; i < 1024; i += 256)
        *(float4*)&cs[i * 4] = *(const float4*)(ctx + (size_t)bh * (DH * DH) + i * 4);
    __syncthreads();

    int t = blockIdx.y * 256 + threadIdx.x;
    size_t off = ((size_t)(b * Tt + t) * Hh + h) * DH;
    const float4* qr4 = (const float4*)(q + off);

    float4 acc[16];
    #pragma unroll
    for (int j = 0; j < 16; j++) acc[j] = make_float4(0.f, 0.f, 0.f, 0.f);

    #pragma unroll 4
    for (int j4 = 0; j4 < 16; j4++) {
        float4 qv = qr4[j4];
        int d0 = j4 * 4;
        #pragma unroll
        for (int dd = 0; dd < 4; dd++) {
            float qd = (dd == 0) ? qv.x : (dd == 1) ? qv.y : (dd == 2) ? qv.z : qv.w;
            const float4* crow = (const float4*)(cs + (d0 + dd) * DH);
            #pragma unroll
            for (int j = 0; j < 16; j++) {
                float4 c = crow[j];
                acc[j].x += qd * c.x;
                acc[j].y += qd * c.y;
                acc[j].z += qd * c.z;
                acc[j].w += qd * c.w;
            }
        }
    }
    float4* yr = (float4*)(y + off);
    #pragma unroll
    for (int j = 0; j < 16; j++) yr[j] = acc[j];
}

// ---------------- emb path: ss[b, 0:2048] = silu(emb[b]) @ emb_W + emb_b ----------------
__global__ __launch_bounds__(256)
void emb_kernel(const float* __restrict__ emb, const float* __restrict__ W,
                const float* __restrict__ eb, float* __restrict__ ss)
{
    int b = blockIdx.y;
    int n = blockIdx.x * 256 + threadIdx.x;   // 0..2047
    __shared__ float es[1024];
    for (int i = threadIdx.x; i < 1024; i += 256) {
        float e = emb[b * 1024 + i];
        es[i] = siluf(e);
    }
    __syncthreads();
    float acc = eb[n];
    #pragma unroll 4
    for (int kk = 0; kk < 1024; kk++)
        acc += es[kk] * W[(size_t)kk * 2048 + n];
    ss[b * 2048 + n] = acc;
}

// ---------------- LN2 + modulation + silu: y -> h ----------------
__global__ __launch_bounds__(256)
void ln2_kernel(const float* __restrict__ y, const float* __restrict__ g,
                const float* __restrict__ bb, const float* __restrict__ ss,
                float* __restrict__ h)
{
    const int row = blockIdx.x;
    const int b = row >> 12;                  // / 4096
    const float* yr = y + (size_t)row * Dd;
    float4 xv = *(const float4*)(yr + threadIdx.x * 4);
    float s  = xv.x + xv.y + xv.z + xv.w;
    float s2 = xv.x*xv.x + xv.y*xv.y + xv.z*xv.z + xv.w*xv.w;

    __shared__ float sh1[8], sh2[8], bc[2];
    s = warpSum(s); s2 = warpSum(s2);
    int w = threadIdx.x >> 5;
    if ((threadIdx.x & 31) == 0) { sh1[w] = s; sh2[w] = s2; }
    __syncthreads();
    if (threadIdx.x == 0) {
        float a = 0.f, c = 0.f;
        #pragma unroll
        for (int i = 0; i < 8; i++) { a += sh1[i]; c += sh2[i]; }
        bc[0] = a; bc[1] = c;
    }
    __syncthreads();
    float mu  = bc[0] * (1.0f / Dd);
    float var = bc[1] * (1.0f / Dd) - mu * mu;
    float inv = rsqrtf(var + 1e-5f);

    int d = threadIdx.x * 4;
    float4 gv = *(const float4*)(g + d);
    float4 bv = *(const float4*)(bb + d);
    float4 sc = *(const float4*)(ss + b * 2048 + d);
    float4 sf = *(const float4*)(ss + b * 2048 + 1024 + d);
    float4 o;
    o.x = siluf(((xv.x - mu) * inv * gv.x + bv.x) * (1.0f + sc.x) + sf.x);
    o.y = siluf(((xv.y - mu) * inv * gv.y + bv.y) * (1.0f + sc.y) + sf.y);
    o.z = siluf(((xv.z - mu) * inv * gv.z + bv.z) * (1.0f + sc.z) + sf.z);
    o.w = siluf(((xv.w - mu) * inv * gv.w + bv.w) * (1.0f + sc.w) + sf.w);
    *(float4*)(h + (size_t)row * Dd + d) = o;
}

// ---------------- launch ----------------
extern "C" void kernel_launch(void* const* d_in, const int* in_sizes, int n_in,
                              void* d_out, int out_size)
{
    const float* x        = (const float*)d_in[0];
    const float* emb      = (const float*)d_in[1];
    const float* gate_msa = (const float*)d_in[2];
    const float* norm_g   = (const float*)d_in[3];
    const float* norm_b   = (const float*)d_in[4];
    const float* Wq       = (const float*)d_in[5];
    const float* bq       = (const float*)d_in[6];
    const float* Wk       = (const float*)d_in[7];
    const float* bk       = (const float*)d_in[8];
    const float* Wv       = (const float*)d_in[9];
    const float* bv       = (const float*)d_in[10];
    const float* emb_W    = (const float*)d_in[11];
    const float* emb_b    = (const float*)d_in[12];
    const float* sn_g     = (const float*)d_in[13];
    const float* sn_b     = (const float*)d_in[14];
    const float* out_W    = (const float*)d_in[15];
    const float* out_b    = (const float*)d_in[16];
    float* out = (float*)d_out;

    float *xn, *q, *k, *v, *y, *h, *ctx, *ss, *pm, *ps, *gm, *gs;
    cudaGetSymbolAddress((void**)&xn,  g_xn);
    cudaGetSymbolAddress((void**)&q,   g_q);
    cudaGetSymbolAddress((void**)&k,   g_k);
    cudaGetSymbolAddress((void**)&v,   g_v);
    cudaGetSymbolAddress((void**)&y,   g_y);
    cudaGetSymbolAddress((void**)&h,   g_h);
    cudaGetSymbolAddress((void**)&ctx, g_ctx);
    cudaGetSymbolAddress((void**)&ss,  g_ss);
    cudaGetSymbolAddress((void**)&pm,  g_pm);
    cudaGetSymbolAddress((void**)&ps,  g_ps);
    cudaGetSymbolAddress((void**)&gm,  g_m);
    cudaGetSymbolAddress((void**)&gs,  g_s);

    // 1. LayerNorm
    ln1_kernel<<<Mm, 256>>>(x, norm_g, norm_b, xn);

    // 2-4. Q/K/V projections
    dim3 gg(Dd / 128, Mm / 128);
    sgemm_k<0><<<gg, 256>>>(xn, Wq, bq, q, nullptr, nullptr, Mm, Dd, Dd, Tt);
    sgemm_k<0><<<gg, 256>>>(xn, Wk, bk, k, nullptr, nullptr, Mm, Dd, Dd, Tt);
    sgemm_k<0><<<gg, 256>>>(xn, Wv, bv, v, nullptr, nullptr, Mm, Dd, Dd, Tt);

    // 5. q feature softmax (in place)
    qsm_kernel<<<(Bb * Tt * Hh) / 8, 256>>>(q);

    // 6-8. k temporal softmax (in place)
    ksm_part<<<dim3(16, 8), 256>>>(k, pm, ps);
    ksm_comb<<<16, 256>>>(pm, ps, gm, gs);
    ksm_norm<<<NELEM / 1024, 256>>>(k, gm, gs);

    // 9-10. context
    zero_kernel<<<1024, 256>>>(ctx, Bb * Hh * DH * DH);
    ctx_kernel<<<dim3(Bb * Hh, 8), 256>>>(k, v, ctx);

    // 11. y = q @ ctx
    y_kernel<<<dim3(Bb * Hh, Tt / 256), 256>>>(q, ctx, y);

    // 12. emb MLP -> scale/shift
    emb_kernel<<<dim3(8, Bb), 256>>>(emb, emb_W, emb_b, ss);

    // 13. LN2 + modulation + silu
    ln2_kernel<<<Mm, 256>>>(y, sn_g, sn_b, ss, h);

    // 14. out projection + residual epilogue
    sgemm_k<1><<<gg, 256>>>(h, out_W, out_b, out, x, gate_msa, Mm, Dd, Dd, Tt);
}

// round 3
// speedup vs baseline: 2.5517x; 2.5517x over previous
#include <cuda_runtime.h>
#include <math.h>
#include <cstdint>

// Problem constants
#define Bb   4
#define Tt   4096
#define Dd   1024
#define Hh   16
#define DH   64
#define Mm   (Bb*Tt)          // 16384 rows
#define NELEM (Mm*Dd)         // 16,777,216

// ---------------- scratch (device globals; no allocation allowed) -------------
__device__ float g_xn [NELEM];
__device__ float g_q  [NELEM];
__device__ float g_k  [NELEM];
__device__ float g_v  [NELEM];
__device__ float g_y  [NELEM];
__device__ float g_h  [NELEM];
__device__ float g_wt [4*Dd*Dd];          // transposed+tf32-rounded weights
__device__ float g_ctx[Bb*Hh*DH*DH];
__device__ float g_ss [Bb*2*Dd];
__device__ float g_pm [8*Bb*Dd];
__device__ float g_ps [8*Bb*Dd];
__device__ float g_m  [Bb*Dd];
__device__ float g_s  [Bb*Dd];

// ---------------- helpers ----------------
__device__ __forceinline__ float warpSum(float v) {
    #pragma unroll
    for (int o = 16; o > 0; o >>= 1) v += __shfl_xor_sync(0xffffffffu, v, o);
    return v;
}
__device__ __forceinline__ float warpMax(float v) {
    #pragma unroll
    for (int o = 16; o > 0; o >>= 1) v = fmaxf(v, __shfl_xor_sync(0xffffffffu, v, o));
    return v;
}
__device__ __forceinline__ float siluf(float v) { return v / (1.0f + expf(-v)); }

__device__ __forceinline__ float tf32r(float x) {
    uint32_t u;
    asm("cvt.rna.tf32.f32 %0, %1;" : "=r"(u) : "f"(x));
    return __uint_as_float(u);
}

#define CP_ASYNC16(dst, src) \
    asm volatile("cp.async.cg.shared.global [%0], [%1], 16;" :: "r"(dst), "l"(src))
#define CP_COMMIT() asm volatile("cp.async.commit_group;" ::: "memory")
#define CP_WAIT(n)  asm volatile("cp.async.wait_group %0;" :: "n"(n) : "memory")

__device__ __forceinline__ uint32_t smem_u32(const void* p) {
    uint32_t a;
    asm("{ .reg .u64 t; cvta.to.shared.u64 t, %1; cvt.u32.u64 %0, t; }" : "=r"(a) : "l"(p));
    return a;
}

__device__ __forceinline__ void mma_tf32(float* c, const uint32_t* a, uint32_t b0, uint32_t b1) {
    asm volatile(
        "mma.sync.aligned.m16n8k8.row.col.f32.tf32.tf32.f32 "
        "{%0,%1,%2,%3}, {%4,%5,%6,%7}, {%8,%9}, {%0,%1,%2,%3};"
        : "+f"(c[0]), "+f"(c[1]), "+f"(c[2]), "+f"(c[3])
        : "r"(a[0]), "r"(a[1]), "r"(a[2]), "r"(a[3]), "r"(b0), "r"(b1));
}

// ================= tf32 mma.sync GEMM: C[M,N] = A[M,K] @ Bt[N,K]^T + bias =================
// Tile 128x128x32, 8 warps (4x2), warp tile 32x64, 4-stage cp.async pipeline.
#define BM 128
#define BN 128
#define BK 32
#define GSTG 4
#define LDA 36                 // padded row (floats): conflict-free frag loads
#define ASTG (BM*LDA)          // 4608 floats per A stage
#define BSTG (BN*LDA)
#define NIT  (Dd/BK)           // 32
#define GSMEM (GSTG*(ASTG+BSTG)*4)   // 147456 bytes

template<int EPI>
__global__ void __launch_bounds__(256, 1)
tgemm_k(const float* __restrict__ A, const float* __restrict__ Bt,
        const float* __restrict__ bias, float* __restrict__ C,
        const float* __restrict__ resid, const float* __restrict__ gate)
{
    extern __shared__ float sm[];
    float* smA = sm;
    float* smB = sm + GSTG * ASTG;

    const int tid  = threadIdx.x;
    const int wid  = tid >> 5;
    const int lane = tid & 31;
    const int g    = lane >> 2;
    const int tig  = lane & 3;
    const int wm   = wid >> 1;       // 0..3
    const int wn   = wid & 1;        // 0..1
    const int cRow = blockIdx.y * BM;
    const int cCol = blockIdx.x * BN;

    // producer addressing: 256 threads, 8 chunks(16B)/row, 32 rows/pass, 4 passes
    const int prow = tid >> 3;       // 0..31
    const int pch  = tid & 7;        // 0..7
    const uint32_t sA0 = smem_u32(smA) + (uint32_t)(prow * LDA + pch * 4) * 4;
    const uint32_t sB0 = smem_u32(smB) + (uint32_t)(prow * LDA + pch * 4) * 4;
    const float* gA = A  + (size_t)(cRow + prow) * Dd + pch * 4;
    const float* gB = Bt + (size_t)(cCol + prow) * Dd + pch * 4;

    #define LOAD_STAGE(it) do { \
        int _s = (it) & (GSTG - 1); int _k0 = (it) * BK; \
        uint32_t _sa = sA0 + (uint32_t)(_s * ASTG) * 4; \
        uint32_t _sb = sB0 + (uint32_t)(_s * BSTG) * 4; \
        _Pragma("unroll") \
        for (int _p = 0; _p < 4; _p++) { \
            CP_ASYNC16(_sa + _p * 32 * LDA * 4, gA + (size_t)_p * 32 * Dd + _k0); \
            CP_ASYNC16(_sb + _p * 32 * LDA * 4, gB + (size_t)_p * 32 * Dd + _k0); \
        } \
        CP_COMMIT(); \
    } while (0)

    LOAD_STAGE(0); LOAD_STAGE(1); LOAD_STAGE(2);

    float acc[2][8][4] = {};

    for (int it = 0; it < NIT; ++it) {
        if (it < NIT - 2)      CP_WAIT(2);
        else if (it == NIT-2)  CP_WAIT(1);
        else                   CP_WAIT(0);
        __syncthreads();
        if (it + 3 < NIT) LOAD_STAGE(it + 3);

        const float* As = smA + (it & (GSTG-1)) * ASTG;
        const float* Bs = smB + (it & (GSTG-1)) * BSTG;
        #pragma unroll
        for (int ks = 0; ks < 4; ks++) {
            const int kb = ks * 8;
            uint32_t a[2][4];
            #pragma unroll
            for (int mt = 0; mt < 2; mt++) {
                const float* ap = As + (wm*32 + mt*16 + g) * LDA + kb + tig;
                a[mt][0] = __float_as_uint(ap[0]);
                a[mt][1] = __float_as_uint(ap[8*LDA]);
                a[mt][2] = __float_as_uint(ap[4]);
                a[mt][3] = __float_as_uint(ap[8*LDA + 4]);
            }
            #pragma unroll
            for (int nt = 0; nt < 8; nt++) {
                const float* bp = Bs + (wn*64 + nt*8 + g) * LDA + kb + tig;
                uint32_t b0 = __float_as_uint(bp[0]);
                uint32_t b1 = __float_as_uint(bp[4]);
                mma_tf32(acc[0][nt], a[0], b0, b1);
                mma_tf32(acc[1][nt], a[1], b0, b1);
            }
        }
    }

    // epilogue
    const int bb = cRow >> 12;   // batch index (block fully inside one batch)
    #pragma unroll
    for (int mt = 0; mt < 2; mt++) {
        const int r0 = cRow + wm*32 + mt*16 + g;
        const int r1 = r0 + 8;
        #pragma unroll
        for (int nt = 0; nt < 8; nt++) {
            const int c0 = cCol + wn*64 + nt*8 + tig*2;
            float bx = bias[c0], by = bias[c0+1];
            float2 v0, v1;
            v0.x = acc[mt][nt][0] + bx;  v0.y = acc[mt][nt][1] + by;
            v1.x = acc[mt][nt][2] + bx;  v1.y = acc[mt][nt][3] + by;
            if (EPI == 1) {
                float gx = gate[bb*Dd + c0], gy = gate[bb*Dd + c0 + 1];
                float2 rA = *(const float2*)(resid + (size_t)r0 * Dd + c0);
                float2 rB = *(const float2*)(resid + (size_t)r1 * Dd + c0);
                v0.x = rA.x + gx * v0.x;  v0.y = rA.y + gy * v0.y;
                v1.x = rB.x + gx * v1.x;  v1.y = rB.y + gy * v1.y;
            }
            *(float2*)(C + (size_t)r0 * Dd + c0) = v0;
            *(float2*)(C + (size_t)r1 * Dd + c0) = v1;
        }
    }
    #undef LOAD_STAGE
}

// ---------------- weight transpose + tf32 round: Wt[n,k] = rna(W[k,n]) ----------------
__global__ __launch_bounds__(256)
void transpose_round(const float* __restrict__ W, float* __restrict__ Wt)
{
    __shared__ float t[32][33];
    int x = blockIdx.x * 32 + threadIdx.x;
    int y = blockIdx.y * 32 + threadIdx.y;
    #pragma unroll
    for (int j = 0; j < 32; j += 8)
        t[threadIdx.y + j][threadIdx.x] = W[(size_t)(y + j) * Dd + x];
    __syncthreads();
    int xo = blockIdx.y * 32 + threadIdx.x;
    int yo = blockIdx.x * 32 + threadIdx.y;
    #pragma unroll
    for (int j = 0; j < 32; j += 8)
        Wt[(size_t)(yo + j) * Dd + xo] = tf32r(t[threadIdx.x][threadIdx.y + j]);
}

// ---------------- LayerNorm 1: x -> xn (tf32-rounded) ----------------
__global__ __launch_bounds__(256)
void ln1_kernel(const float* __restrict__ x, const float* __restrict__ g,
                const float* __restrict__ b, float* __restrict__ out)
{
    const int row = blockIdx.x;
    const float* xr = x + (size_t)row * Dd;
    float4 xv = *(const float4*)(xr + threadIdx.x * 4);
    float s  = xv.x + xv.y + xv.z + xv.w;
    float s2 = xv.x*xv.x + xv.y*xv.y + xv.z*xv.z + xv.w*xv.w;

    __shared__ float sh1[8], sh2[8], bc[2];
    s = warpSum(s); s2 = warpSum(s2);
    int w = threadIdx.x >> 5;
    if ((threadIdx.x & 31) == 0) { sh1[w] = s; sh2[w] = s2; }
    __syncthreads();
    if (threadIdx.x == 0) {
        float a = 0.f, c = 0.f;
        #pragma unroll
        for (int i = 0; i < 8; i++) { a += sh1[i]; c += sh2[i]; }
        bc[0] = a; bc[1] = c;
    }
    __syncthreads();
    float mu  = bc[0] * (1.0f / Dd);
    float var = bc[1] * (1.0f / Dd) - mu * mu;
    float inv = rsqrtf(var + 1e-5f);

    int d = threadIdx.x * 4;
    float4 gv = *(const float4*)(g + d);
    float4 bv = *(const float4*)(b + d);
    float4 o;
    o.x = tf32r((xv.x - mu) * inv * gv.x + bv.x);
    o.y = tf32r((xv.y - mu) * inv * gv.y + bv.y);
    o.z = tf32r((xv.z - mu) * inv * gv.z + bv.z);
    o.w = tf32r((xv.w - mu) * inv * gv.w + bv.w);
    *(float4*)(out + (size_t)row * Dd + d) = o;
}

// ---------------- q feature-softmax ----------------
__global__ __launch_bounds__(256)
void qsm_kernel(float* __restrict__ q)
{
    int gwarp = (blockIdx.x * blockDim.x + threadIdx.x) >> 5;
    int lane  = threadIdx.x & 31;
    float2 v = *(float2*)(q + (size_t)gwarp * 64 + lane * 2);
    float m = warpMax(fmaxf(v.x, v.y));
    float e0 = expf(v.x - m), e1 = expf(v.y - m);
    float s = warpSum(e0 + e1);
    float inv = 1.0f / s;
    float2 o; o.x = e0 * inv; o.y = e1 * inv;
    *(float2*)(q + (size_t)gwarp * 64 + lane * 2) = o;
}

// ---------------- k temporal softmax ----------------
__global__ __launch_bounds__(256)
void ksm_part(const float* __restrict__ k, float* __restrict__ pm, float* __restrict__ ps)
{
    int col = blockIdx.x * 256 + threadIdx.x;
    int b = col >> 10, d = col & 1023;
    int t0 = blockIdx.y * (Tt / 8);
    const float* p = k + ((size_t)(b * Tt + t0)) * Dd + d;
    float m = -INFINITY, s = 0.0f;
    #pragma unroll 4
    for (int t = 0; t < Tt / 8; t++) {
        float v = p[(size_t)t * Dd];
        float mn = fmaxf(m, v);
        s = s * expf(m - mn) + expf(v - mn);
        m = mn;
    }
    pm[blockIdx.y * (Bb * Dd) + col] = m;
    ps[blockIdx.y * (Bb * Dd) + col] = s;
}

__global__ __launch_bounds__(256)
void ksm_comb(const float* __restrict__ pm, const float* __restrict__ ps,
              float* __restrict__ gm, float* __restrict__ gs)
{
    int col = blockIdx.x * 256 + threadIdx.x;
    float M = -INFINITY;
    #pragma unroll
    for (int c = 0; c < 8; c++) M = fmaxf(M, pm[c * (Bb * Dd) + col]);
    float S = 0.0f;
    #pragma unroll
    for (int c = 0; c < 8; c++)
        S += ps[c * (Bb * Dd) + col] * expf(pm[c * (Bb * Dd) + col] - M);
    gm[col] = M;
    gs[col] = S;
}

__global__ __launch_bounds__(256)
void ksm_norm(float* __restrict__ k, const float* __restrict__ gm, const float* __restrict__ gs)
{
    size_t i4 = (size_t)blockIdx.x * 256 + threadIdx.x;
    size_t e  = i4 * 4;
    int b = (int)(e >> 22);
    int d = (int)(e & 1023);
    int col = b * 1024 + d;
    float4 v = *(float4*)(k + e);
    float4 m = *(const float4*)(gm + col);
    float4 s = *(const float4*)(gs + col);
    float4 o;
    o.x = expf(v.x - m.x) / s.x;
    o.y = expf(v.y - m.y) / s.y;
    o.z = expf(v.z - m.z) / s.z;
    o.w = expf(v.w - m.w) / s.w;
    *(float4*)(k + e) = o;
}

// ---------------- zero ctx ----------------
__global__ void zero_kernel(float* __restrict__ p, int n)
{
    int i = blockIdx.x * blockDim.x + threadIdx.x;
    if (i < n) p[i] = 0.0f;
}

// ---------------- ctx ----------------
__global__ __launch_bounds__(256)
void ctx_kernel(const float* __restrict__ k, const float* __restrict__ v,
                float* __restrict__ ctx)
{
    int bh = blockIdx.x;
    int b = bh >> 4, h = bh & 15;
    __shared__ float ks[64][64];
    __shared__ float vs[64][64];
    int tr = threadIdx.x >> 4, tc = threadIdx.x & 15;
    float acc[4][4] = {};

    int tbase = blockIdx.y * (Tt / 8);
    for (int tt0 = 0; tt0 < Tt / 8; tt0 += 64) {
        for (int i = threadIdx.x; i < 64 * 16; i += 256) {
            int t  = i >> 4;
            int c4 = (i & 15) * 4;
            size_t off = ((size_t)((b * Tt + tbase + tt0 + t)) * Hh + h) * DH + c4;
            *(float4*)&ks[t][c4] = *(const float4*)(k + off);
            *(float4*)&vs[t][c4] = *(const float4*)(v + off);
        }
        __syncthreads();
        #pragma unroll 8
        for (int t = 0; t < 64; t++) {
            float rk[4], rv[4];
            #pragma unroll
            for (int i = 0; i < 4; i++) rk[i] = ks[t][tr * 4 + i];
            #pragma unroll
            for (int j = 0; j < 4; j++) rv[j] = vs[t][tc * 4 + j];
            #pragma unroll
            for (int i = 0; i < 4; i++)
                #pragma unroll
                for (int j = 0; j < 4; j++)
                    acc[i][j] += rk[i] * rv[j];
        }
        __syncthreads();
    }
    float* c = ctx + (size_t)bh * (DH * DH);
    #pragma unroll
    for (int i = 0; i < 4; i++)
        #pragma unroll
        for (int j = 0; j < 4; j++)
            atomicAdd(&c[(tr * 4 + i) * DH + tc * 4 + j], acc[i][j]);
}

// ---------------- y = q @ ctx ----------------
__global__ __launch_bounds__(256)
void y_kernel(const float* __restrict__ q, const float* __restrict__ ctx,
              float* __restrict__ y)
{
    int bh = blockIdx.x;
    int b = bh >> 4, h = bh & 15;
    __shared__ float cs[DH * DH];
    for (int i = threadIdx.x; i < 1024; i += 256)
        *(float4*)&cs[i * 4] = *(const float4*)(ctx + (size_t)bh * (DH * DH) + i * 4);
    __syncthreads();

    int t = blockIdx.y * 256 + threadIdx.x;
    size_t off = ((size_t)(b * Tt + t) * Hh + h) * DH;
    const float4* qr4 = (const float4*)(q + off);

    float4 acc[16];
    #pragma unroll
    for (int j = 0; j < 16; j++) acc[j] = make_float4(0.f, 0.f, 0.f, 0.f);

    #pragma unroll 4
    for (int j4 = 0; j4 < 16; j4++) {
        float4 qv = qr4[j4];
        int d0 = j4 * 4;
        #pragma unroll
        for (int dd = 0; dd < 4; dd++) {
            float qd = (dd == 0) ? qv.x : (dd == 1) ? qv.y : (dd == 2) ? qv.z : qv.w;
            const float4* crow = (const float4*)(cs + (d0 + dd) * DH);
            #pragma unroll
            for (int j = 0; j < 16; j++) {
                float4 c = crow[j];
                acc[j].x += qd * c.x;
                acc[j].y += qd * c.y;
                acc[j].z += qd * c.z;
                acc[j].w += qd * c.w;
            }
        }
    }
    float4* yr = (float4*)(y + off);
    #pragma unroll
    for (int j = 0; j < 16; j++) yr[j] = acc[j];
}

// ---------------- emb MLP ----------------
__global__ __launch_bounds__(256)
void emb_kernel(const float* __restrict__ emb, const float* __restrict__ W,
                const float* __restrict__ eb, float* __restrict__ ss)
{
    int b = blockIdx.y;
    int n = blockIdx.x * 256 + threadIdx.x;
    __shared__ float es[1024];
    for (int i = threadIdx.x; i < 1024; i += 256) {
        float e = emb[b * 1024 + i];
        es[i] = siluf(e);
    }
    __syncthreads();
    float acc = eb[n];
    #pragma unroll 4
    for (int kk = 0; kk < 1024; kk++)
        acc += es[kk] * W[(size_t)kk * 2048 + n];
    ss[b * 2048 + n] = acc;
}

// ---------------- LN2 + modulation + silu (tf32-rounded) ----------------
__global__ __launch_bounds__(256)
void ln2_kernel(const float* __restrict__ y, const float* __restrict__ g,
                const float* __restrict__ bb, const float* __restrict__ ss,
                float* __restrict__ h)
{
    const int row = blockIdx.x;
    const int b = row >> 12;
    const float* yr = y + (size_t)row * Dd;
    float4 xv = *(const float4*)(yr + threadIdx.x * 4);
    float s  = xv.x + xv.y + xv.z + xv.w;
    float s2 = xv.x*xv.x + xv.y*xv.y + xv.z*xv.z + xv.w*xv.w;

    __shared__ float sh1[8], sh2[8], bc[2];
    s = warpSum(s); s2 = warpSum(s2);
    int w = threadIdx.x >> 5;
    if ((threadIdx.x & 31) == 0) { sh1[w] = s; sh2[w] = s2; }
    __syncthreads();
    if (threadIdx.x == 0) {
        float a = 0.f, c = 0.f;
        #pragma unroll
        for (int i = 0; i < 8; i++) { a += sh1[i]; c += sh2[i]; }
        bc[0] = a; bc[1] = c;
    }
    __syncthreads();
    float mu  = bc[0] * (1.0f / Dd);
    float var = bc[1] * (1.0f / Dd) - mu * mu;
    float inv = rsqrtf(var + 1e-5f);

    int d = threadIdx.x * 4;
    float4 gv = *(const float4*)(g + d);
    float4 bv = *(const float4*)(bb + d);
    float4 sc = *(const float4*)(ss + b * 2048 + d);
    float4 sf = *(const float4*)(ss + b * 2048 + 1024 + d);
    float4 o;
    o.x = tf32r(siluf(((xv.x - mu) * inv * gv.x + bv.x) * (1.0f + sc.x) + sf.x));
    o.y = tf32r(siluf(((xv.y - mu) * inv * gv.y + bv.y) * (1.0f + sc.y) + sf.y));
    o.z = tf32r(siluf(((xv.z - mu) * inv * gv.z + bv.z) * (1.0f + sc.z) + sf.z));
    o.w = tf32r(siluf(((xv.w - mu) * inv * gv.w + bv.w) * (1.0f + sc.w) + sf.w));
    *(float4*)(h + (size_t)row * Dd + d) = o;
}

// ---------------- launch ----------------
extern "C" void kernel_launch(void* const* d_in, const int* in_sizes, int n_in,
                              void* d_out, int out_size)
{
    const float* x        = (const float*)d_in[0];
    const float* emb      = (const float*)d_in[1];
    const float* gate_msa = (const float*)d_in[2];
    const float* norm_g   = (const float*)d_in[3];
    const float* norm_b   = (const float*)d_in[4];
    const float* Wq       = (const float*)d_in[5];
    const float* bq       = (const float*)d_in[6];
    const float* Wk       = (const float*)d_in[7];
    const float* bk       = (const float*)d_in[8];
    const float* Wv       = (const float*)d_in[9];
    const float* bv       = (const float*)d_in[10];
    const float* emb_W    = (const float*)d_in[11];
    const float* emb_b    = (const float*)d_in[12];
    const float* sn_g     = (const float*)d_in[13];
    const float* sn_b     = (const float*)d_in[14];
    const float* out_W    = (const float*)d_in[15];
    const float* out_b    = (const float*)d_in[16];
    float* out = (float*)d_out;

    float *xn, *q, *k, *v, *y, *h, *wt, *ctx, *ss, *pm, *ps, *gm, *gs;
    cudaGetSymbolAddress((void**)&xn,  g_xn);
    cudaGetSymbolAddress((void**)&q,   g_q);
    cudaGetSymbolAddress((void**)&k,   g_k);
    cudaGetSymbolAddress((void**)&v,   g_v);
    cudaGetSymbolAddress((void**)&y,   g_y);
    cudaGetSymbolAddress((void**)&h,   g_h);
    cudaGetSymbolAddress((void**)&wt,  g_wt);
    cudaGetSymbolAddress((void**)&ctx, g_ctx);
    cudaGetSymbolAddress((void**)&ss,  g_ss);
    cudaGetSymbolAddress((void**)&pm,  g_pm);
    cudaGetSymbolAddress((void**)&ps,  g_ps);
    cudaGetSymbolAddress((void**)&gm,  g_m);
    cudaGetSymbolAddress((void**)&gs,  g_s);

    cudaFuncSetAttribute(tgemm_k<0>, cudaFuncAttributeMaxDynamicSharedMemorySize, GSMEM);
    cudaFuncSetAttribute(tgemm_k<1>, cudaFuncAttributeMaxDynamicSharedMemorySize, GSMEM);

    // weight transposes (+ tf32 rounding)
    dim3 tg(32, 32), tb(32, 8);
    transpose_round<<<tg, tb>>>(Wq,    wt + 0 * Dd * Dd);
    transpose_round<<<tg, tb>>>(Wk,    wt + 1 * Dd * Dd);
    transpose_round<<<tg, tb>>>(Wv,    wt + 2 * Dd * Dd);
    transpose_round<<<tg, tb>>>(out_W, wt + 3 * Dd * Dd);

    // 1. LayerNorm
    ln1_kernel<<<Mm, 256>>>(x, norm_g, norm_b, xn);

    // 2-4. Q/K/V projections (tf32 mma.sync)
    dim3 gg(Dd / 128, Mm / 128);
    tgemm_k<0><<<gg, 256, GSMEM>>>(xn, wt + 0 * Dd * Dd, bq, q, nullptr, nullptr);
    tgemm_k<0><<<gg, 256, GSMEM>>>(xn, wt + 1 * Dd * Dd, bk, k, nullptr, nullptr);
    tgemm_k<0><<<gg, 256, GSMEM>>>(xn, wt + 2 * Dd * Dd, bv, v, nullptr, nullptr);

    // 5. q feature softmax
    qsm_kernel<<<(Bb * Tt * Hh) / 8, 256>>>(q);

    // 6-8. k temporal softmax
    ksm_part<<<dim3(16, 8), 256>>>(k, pm, ps);
    ksm_comb<<<16, 256>>>(pm, ps, gm, gs);
    ksm_norm<<<NELEM / 1024, 256>>>(k, gm, gs);

    // 9-10. context
    zero_kernel<<<1024, 256>>>(ctx, Bb * Hh * DH * DH);
    ctx_kernel<<<dim3(Bb * Hh, 8), 256>>>(k, v, ctx);

    // 11. y = q @ ctx
    y_kernel<<<dim3(Bb * Hh, Tt / 256), 256>>>(q, ctx, y);

    // 12. emb MLP
    emb_kernel<<<dim3(8, Bb), 256>>>(emb, emb_W, emb_b, ss);

    // 13. LN2 + modulation + silu
    ln2_kernel<<<Mm, 256>>>(y, sn_g, sn_b, ss, h);

    // 14. out projection + residual epilogue (tf32 mma.sync)
    tgemm_k<1><<<gg, 256, GSMEM>>>(h, wt + 3 * Dd * Dd, out_b, out, x, gate_msa);
}